// round 2
// baseline (speedup 1.0000x reference)
#include <cuda_runtime.h>

// Fused loss: CE + Dice + Focal + 0.5 * Lovasz
// logits: [4, 19, 512, 1024] f32; masks: [4, 512, 1024] int32 (JAX x64-off
// demotes int64 -> int32); out: scalar f32.

#define NC 19
#define HW (512 * 1024)           // 524288 = 1<<19
#define NPIX (4 * HW)             // 2097152
#define NBUCK 65536
#define BSCALE 8192.0f            // buckets per unit error; range [0, 8)
#define HIST_WORDS (NC * NBUCK)   // 1245184
#define LOGITS_ELEMS (4 * NC * HW)

// Accumulators (device globals, zeroed each launch by zero_kernel)
__device__ unsigned g_hist[HIST_WORDS];   // per class: (fg<<16)|bg per bucket
__device__ double   g_acc[48];            // [0]=ce [1]=focal [2]=lovasz [3..21]=sum_prob [22..40]=inter
__device__ unsigned g_cnt[NC];            // per-class fg pixel count (P)

// ---------------------------------------------------------------------------
__global__ void zero_kernel() {
    unsigned i = blockIdx.x * blockDim.x + threadIdx.x;
    if (i < HIST_WORDS) g_hist[i] = 0u;
    if (i < 48) g_acc[i] = 0.0;
    if (i < NC) g_cnt[i] = 0u;
}

// ---------------------------------------------------------------------------
// Main fused pass: each thread processes 2 consecutive pixels (float2 loads).
__global__ void __launch_bounds__(256) main_kernel(
    const float* __restrict__ logits, const int* __restrict__ masks)
{
    __shared__ float s_sp[NC];     // sum of probs per class
    __shared__ float s_in[NC];     // intersection (prob at target class)
    __shared__ unsigned s_ct[NC];  // class pixel counts
    __shared__ float s_ce, s_fo;

    const int tid = threadIdx.x;
    if (tid < NC) { s_sp[tid] = 0.f; s_in[tid] = 0.f; s_ct[tid] = 0u; }
    if (tid == 0) { s_ce = 0.f; s_fo = 0.f; }
    __syncthreads();

    const unsigned gidx = blockIdx.x * 256u + tid;   // group of 2 pixels
    const unsigned p0 = gidx * 2u;
    const unsigned b  = p0 >> 19;
    const unsigned hw = p0 & (HW - 1);
    const float* base = logits + ((size_t)(b * NC) << 19) + hw;

    int2 mm = reinterpret_cast<const int2*>(masks)[gidx];
    const int t0 = min(max(mm.x, 0), NC - 1);
    const int t1 = min(max(mm.y, 0), NC - 1);

    float2 l[NC];
    float mx0 = -1e30f, mx1 = -1e30f;
#pragma unroll
    for (int c = 0; c < NC; c++) {
        float2 v = *reinterpret_cast<const float2*>(base + ((size_t)c << 19));
        l[c] = v;
        mx0 = fmaxf(mx0, v.x);
        mx1 = fmaxf(mx1, v.y);
    }

    float s0 = 0.f, s1 = 0.f;
    float lt0 = 0.f, lt1 = 0.f;
#pragma unroll
    for (int c = 0; c < NC; c++) {
        float lx = l[c].x, ly = l[c].y;
        float e0 = __expf(lx - mx0);
        float e1 = __expf(ly - mx1);
        s0 += e0; s1 += e1;
        if (c == t0) lt0 = lx;
        if (c == t1) lt1 = ly;
        // Lovasz hinge errors + histogram (only err > 0 matters)
        float er0 = (c == t0) ? (1.f - lx) : (1.f + lx);
        float er1 = (c == t1) ? (1.f - ly) : (1.f + ly);
        if (er0 > 0.f) {
            unsigned bk = min((unsigned)(er0 * BSCALE), (unsigned)(NBUCK - 1));
            atomicAdd(&g_hist[((unsigned)c << 16) | bk], (c == t0) ? 65536u : 1u);
        }
        if (er1 > 0.f) {
            unsigned bk = min((unsigned)(er1 * BSCALE), (unsigned)(NBUCK - 1));
            atomicAdd(&g_hist[((unsigned)c << 16) | bk], (c == t1) ? 65536u : 1u);
        }
        l[c].x = e0; l[c].y = e1;   // keep exp values for prob pass
    }

    const float inv0 = __fdividef(1.f, s0);
    const float inv1 = __fdividef(1.f, s1);
    const float lz0 = mx0 + __logf(s0);
    const float lz1 = mx1 + __logf(s1);

    // CE / Focal for the two pixels
    const float logpt0 = lt0 - lz0;
    const float logpt1 = lt1 - lz1;
    const float pt0 = __expf(logpt0);
    const float pt1 = __expf(logpt1);
    float ce_l = -(logpt0 + logpt1);
    float fo_l = -0.25f * ((1.f - pt0) * (1.f - pt0) * logpt0 +
                           (1.f - pt1) * (1.f - pt1) * logpt1);

    atomicAdd(&s_in[t0], pt0);
    atomicAdd(&s_in[t1], pt1);
    atomicAdd(&s_ct[t0], 1u);
    atomicAdd(&s_ct[t1], 1u);

    const int lane = tid & 31;
    // per-class sum of probs: warp reduce then lane0 -> shared
#pragma unroll
    for (int c = 0; c < NC; c++) {
        float v = l[c].x * inv0 + l[c].y * inv1;
#pragma unroll
        for (int d = 16; d; d >>= 1) v += __shfl_down_sync(0xffffffffu, v, d);
        if (lane == 0) atomicAdd(&s_sp[c], v);
    }
#pragma unroll
    for (int d = 16; d; d >>= 1) {
        ce_l += __shfl_down_sync(0xffffffffu, ce_l, d);
        fo_l += __shfl_down_sync(0xffffffffu, fo_l, d);
    }
    if (lane == 0) {
        atomicAdd(&s_ce, ce_l);
        atomicAdd(&s_fo, fo_l);
    }
    __syncthreads();

    if (tid < NC) {
        atomicAdd(&g_acc[3 + tid], (double)s_sp[tid]);
        atomicAdd(&g_acc[22 + tid], (double)s_in[tid]);
        atomicAdd(&g_cnt[tid], s_ct[tid]);
    }
    if (tid == 32) atomicAdd(&g_acc[0], (double)s_ce);
    if (tid == 33) atomicAdd(&g_acc[1], (double)s_fo);
}

// ---------------------------------------------------------------------------
// Per-class descending scan over the error histogram -> Lovasz per-class sum.
__global__ void __launch_bounds__(1024) scan_kernel() {
    const int c = blockIdx.x;
    const int tid = threadIdx.x;
    const unsigned P = g_cnt[c];
    if (P == 0) return;   // class absent -> excluded (uniform for block)

    __shared__ unsigned wF[32], wB[32];
    __shared__ unsigned carF, carB;
    if (tid == 0) { carF = 0u; carB = 0u; }
    __syncthreads();

    const unsigned* hist = g_hist + ((unsigned)c << 16);
    const double Pd = (double)P;
    double acc = 0.0;

    for (int chunk = 0; chunk < NBUCK; chunk += 1024) {
        const int idx = (NBUCK - 1) - (chunk + tid);   // descending error
        const unsigned cnt = hist[idx];
        const unsigned f = cnt >> 16;
        const unsigned gq = cnt & 0xFFFFu;

        // inclusive warp scan (tid order == descending bucket order)
        unsigned fi = f, gi = gq;
#pragma unroll
        for (int d = 1; d < 32; d <<= 1) {
            unsigned a = __shfl_up_sync(0xffffffffu, fi, d);
            unsigned bb = __shfl_up_sync(0xffffffffu, gi, d);
            if ((tid & 31) >= d) { fi += a; gi += bb; }
        }
        const int w = tid >> 5;
        if ((tid & 31) == 31) { wF[w] = fi; wB[w] = gi; }
        __syncthreads();

        unsigned aF = carF, aB = carB;
        for (int k = 0; k < w; k++) { aF += wF[k]; aB += wB[k]; }

        if (cnt) {
            const double Fi = (double)(aF + fi);
            const double Bi = (double)(aB + gi);
            const double Fe = Fi - (double)f;
            const double Be = Bi - (double)gq;
            const double e_rep = ((double)idx + 0.5) * (1.0 / 8192.0);
            // contribution = e_rep * (J_inclusive - J_exclusive),
            // J(F,B) = 1 - (P-F)/(P+B)
            acc += e_rep * ((Pd - Fe) / (Pd + Be) - (Pd - Fi) / (Pd + Bi));
        }
        __syncthreads();
        if (tid == 0) {
            unsigned sF = 0u, sB = 0u;
#pragma unroll
            for (int k = 0; k < 32; k++) { sF += wF[k]; sB += wB[k]; }
            carF += sF; carB += sB;
        }
        __syncthreads();
    }

    // block reduce acc (double)
    __shared__ double red[32];
#pragma unroll
    for (int d = 16; d; d >>= 1) acc += __shfl_down_sync(0xffffffffu, acc, d);
    if ((tid & 31) == 0) red[tid >> 5] = acc;
    __syncthreads();
    if (tid < 32) {
        double v = red[tid];
#pragma unroll
        for (int d = 16; d; d >>= 1) v += __shfl_down_sync(0xffffffffu, v, d);
        if (tid == 0) atomicAdd(&g_acc[2], v);
    }
}

// ---------------------------------------------------------------------------
__global__ void final_kernel(float* __restrict__ out) {
    if (threadIdx.x == 0 && blockIdx.x == 0) {
        const double Nd = (double)NPIX;
        const double ce = g_acc[0] / Nd;
        const double fo = g_acc[1] / Nd;
        double dsum = 0.0, np = 0.0;
        for (int c = 0; c < NC; c++) {
            if (g_cnt[c] > 0u) {
                const double u = g_acc[3 + c] + (double)g_cnt[c];
                dsum += (2.0 * g_acc[22 + c] + 1e-8) / (u + 1e-8);
                np += 1.0;
            }
        }
        const double dice = (np > 0.0) ? (1.0 - dsum / np) : 1.0;
        const double lov = g_acc[2] / (double)NC;
        out[0] = (float)(ce + dice + fo + 0.5 * lov);
    }
}

// ---------------------------------------------------------------------------
extern "C" void kernel_launch(void* const* d_in, const int* in_sizes, int n_in,
                              void* d_out, int out_size)
{
    // Robust input binding: logits is the big buffer (39,845,888 f32).
    const float* logits;
    const int* masks;
    if (in_sizes[0] == LOGITS_ELEMS) {
        logits = (const float*)d_in[0];
        masks  = (const int*)d_in[1];
    } else {
        logits = (const float*)d_in[1];
        masks  = (const int*)d_in[0];
    }
    float* out = (float*)d_out;

    zero_kernel<<<(HIST_WORDS + 255) / 256, 256>>>();
    main_kernel<<<NPIX / 2 / 256, 256>>>(logits, masks);
    scan_kernel<<<NC, 1024>>>();
    final_kernel<<<1, 32>>>(out);
}